// round 16
// baseline (speedup 1.0000x reference)
#include <cuda_runtime.h>
#include <cuda_fp16.h>
#include <cstdint>

#define D 128
#define NSRC 50000
#define NDST 50000
#define NEDGE 640000
#define NTILES (NEDGE / 128)
#define NEG_SLOPE 0.01f

// ---------------- device scratch (static, no allocation) ----------------
__device__ float g_hs[NSRC * D];
__device__ float g_hd[NDST * D];
__device__ float g_nf[NDST * D];
__device__ float g_score[NEDGE];   // CSR-ordered scores
__device__ int g_srcp[NEDGE];      // CSR-ordered src indices
__device__ int g_dstp[NEDGE];      // CSR-ordered dst indices
__device__ int g_count[NDST];
__device__ int g_offset[NDST + 1];
__device__ int g_cursor[NDST];
__device__ int g_bsums[64];
__device__ int g_bsums2[64];

__device__ __forceinline__ float lrelu(float x) { return x > 0.f ? x : NEG_SLOPE * x; }

// Swizzled element offset inside a [128 rows x 128 cols] f16 tile.
__device__ __forceinline__ uint32_t swz_off(int r, int c) {
    return (uint32_t)((r << 7) + ((((c >> 3) ^ (r & 7)) << 3) + (c & 7)));
}

__device__ __forceinline__ uint32_t smem_u32(const void* p) {
    uint32_t a;
    asm("{ .reg .u64 t; cvta.to.shared.u64 t, %1; cvt.u32.u64 %0, t; }" : "=r"(a) : "l"(p));
    return a;
}

#define LDSM_X4(r0, r1, r2, r3, addr) \
    asm volatile("ldmatrix.sync.aligned.m8n8.x4.shared.b16 {%0,%1,%2,%3}, [%4];" \
        : "=r"(r0), "=r"(r1), "=r"(r2), "=r"(r3) : "r"(addr))
#define LDSM_X4_T(r0, r1, r2, r3, addr) \
    asm volatile("ldmatrix.sync.aligned.m8n8.x4.trans.shared.b16 {%0,%1,%2,%3}, [%4];" \
        : "=r"(r0), "=r"(r1), "=r"(r2), "=r"(r3) : "r"(addr))
// fp32-accumulator HMMA (hi term)
#define MMA_F16(c0, c1, c2, c3, a0, a1, a2, a3, b0, b1) \
    asm volatile("mma.sync.aligned.m16n8k16.row.col.f32.f16.f16.f32 " \
        "{%0,%1,%2,%3}, {%4,%5,%6,%7}, {%8,%9}, {%0,%1,%2,%3};" \
        : "+f"(c0), "+f"(c1), "+f"(c2), "+f"(c3) \
        : "r"(a0), "r"(a1), "r"(a2), "r"(a3), "r"(b0), "r"(b1))
// fp16-accumulator HMMA (lo/residual term; 2x rate, error negligible at lo scale)
#define MMA_F16_ACCH(c0, c1, a0, a1, a2, a3, b0, b1) \
    asm volatile("mma.sync.aligned.m16n8k16.row.col.f16.f16.f16.f16 " \
        "{%0,%1}, {%2,%3,%4,%5}, {%6,%7}, {%0,%1};" \
        : "+r"(c0), "+r"(c1) \
        : "r"(a0), "r"(a1), "r"(a2), "r"(a3), "r"(b0), "r"(b1))

__device__ __forceinline__ float h2lo(uint32_t w) {
    __half2 h = *reinterpret_cast<__half2*>(&w);
    return __low2float(h);
}
__device__ __forceinline__ float h2hi(uint32_t w) {
    __half2 h = *reinterpret_cast<__half2*>(&w);
    return __high2float(h);
}

// split two fp32 into fp16 hi pair + fp16 residual pair (packed f16x2 words)
__device__ __forceinline__ void split2h(float t0, float t1, uint32_t& hi, uint32_t& lo) {
    __half2 h = __floats2half2_rn(t0, t1);
    float h0 = __low2float(h), h1 = __high2float(h);
    __half2 l = __floats2half2_rn(t0 - h0, t1 - h1);
    hi = *reinterpret_cast<uint32_t*>(&h);
    lo = *reinterpret_cast<uint32_t*>(&l);
}

// =======================================================================
// Node GEMM via HMMA (fp16 hi term fp32-acc + residual fp16-acc).
// =======================================================================
#define GN_SMEM (96 * 1024 + 512)

__device__ __forceinline__ void gemm_node_body(
    const float* __restrict__ A, const float* __restrict__ W,
    const float* __restrict__ bias, float* __restrict__ Out,
    int nrows, int act, int blk, char* smc)
{
    char* sW    = smc;
    char* sA_hi = smc + 32768;
    char* sA_lo = smc + 65536;
    float* sbias = (float*)(smc + 98304);

    const int tid = threadIdx.x;
    const int wid = tid >> 5;
    const int lane = tid & 31;
    const int row0 = blk * 128;

    for (int i = tid; i < D * D; i += 256) {
        int k = i >> 7, n = i & 127;
        ((__half*)sW)[swz_off(k, n)] = __float2half_rn(W[i]);
    }
    {
        const float4* A4 = (const float4*)A;
#pragma unroll 4
        for (int it = 0; it < 16; ++it) {
            int idx = it * 256 + tid;
            int r = idx >> 5, c4 = idx & 31;
            int gr = row0 + r;
            float4 v = make_float4(0.f, 0.f, 0.f, 0.f);
            if (gr < nrows) v = A4[gr * 32 + c4];
            uint32_t hi01, lo01, hi23, lo23;
            split2h(v.x, v.y, hi01, lo01);
            split2h(v.z, v.w, hi23, lo23);
            uint32_t off = swz_off(r, c4 * 4) * 2;
            *(uint2*)(sA_hi + off) = make_uint2(hi01, hi23);
            *(uint2*)(sA_lo + off) = make_uint2(lo01, lo23);
        }
    }
    if (tid < 128) sbias[tid] = bias[tid];
    __syncthreads();

    const int rg = wid & 3, cg = wid >> 2;
    const int row_lo = (lane & 7) + ((lane >> 3) & 1) * 8;
    const int acg = (lane >> 4) & 1;
    const int x7 = lane & 7;
    const int g = lane >> 2;
    const int tig = lane & 3;
    const uint32_t sA_hi_b = smem_u32(sA_hi);
    const uint32_t sA_lo_b = smem_u32(sA_lo);
    const uint32_t sW_b = smem_u32(sW);

    float acc[2][8][4];
    uint32_t lacc[2][8][2];
#pragma unroll
    for (int rc = 0; rc < 2; ++rc)
#pragma unroll
        for (int np = 0; np < 8; ++np) {
#pragma unroll
            for (int j = 0; j < 4; ++j) acc[rc][np][j] = 0.f;
            lacc[rc][np][0] = 0u; lacc[rc][np][1] = 0u;
        }

#pragma unroll
    for (int ks = 0; ks < 8; ++ks) {
        uint32_t ah[2][4], al[2][4];
#pragma unroll
        for (int rc = 0; rc < 2; ++rc) {
            uint32_t a_off = (uint32_t)((rg * 32 + rc * 16 + row_lo) << 8)
                           + (uint32_t)((((2 * ks + acg) ^ x7) << 4));
            LDSM_X4(ah[rc][0], ah[rc][1], ah[rc][2], ah[rc][3], sA_hi_b + a_off);
            LDSM_X4(al[rc][0], al[rc][1], al[rc][2], al[rc][3], sA_lo_b + a_off);
        }
        const int bk = ks * 16 + row_lo;
#pragma unroll
        for (int p = 0; p < 4; ++p) {
            int cidx = 2 * (cg * 4 + p) + acg;
            uint32_t b_off = (uint32_t)(bk << 8) + (uint32_t)(((cidx ^ x7) << 4));
            uint32_t bh0, bh1, bh2, bh3;
            LDSM_X4_T(bh0, bh1, bh2, bh3, sW_b + b_off);
#pragma unroll
            for (int rc = 0; rc < 2; ++rc) {
                float* c0 = acc[rc][2 * p];
                float* c1 = acc[rc][2 * p + 1];
                MMA_F16(c0[0], c0[1], c0[2], c0[3], ah[rc][0], ah[rc][1], ah[rc][2], ah[rc][3], bh0, bh1);
                MMA_F16_ACCH(lacc[rc][2 * p][0], lacc[rc][2 * p][1],
                             al[rc][0], al[rc][1], al[rc][2], al[rc][3], bh0, bh1);
                MMA_F16(c1[0], c1[1], c1[2], c1[3], ah[rc][0], ah[rc][1], ah[rc][2], ah[rc][3], bh2, bh3);
                MMA_F16_ACCH(lacc[rc][2 * p + 1][0], lacc[rc][2 * p + 1][1],
                             al[rc][0], al[rc][1], al[rc][2], al[rc][3], bh2, bh3);
            }
        }
    }

#pragma unroll
    for (int rc = 0; rc < 2; ++rc) {
#pragma unroll
        for (int np = 0; np < 8; ++np) {
            int n = cg * 64 + np * 8 + tig * 2;
            float b0 = sbias[n], b1 = sbias[n + 1];
            int r1 = row0 + rg * 32 + rc * 16 + g;
            float v0 = acc[rc][np][0] + h2lo(lacc[rc][np][0]) + b0;
            float v1 = acc[rc][np][1] + h2hi(lacc[rc][np][0]) + b1;
            float v2 = acc[rc][np][2] + h2lo(lacc[rc][np][1]) + b0;
            float v3 = acc[rc][np][3] + h2hi(lacc[rc][np][1]) + b1;
            if (act) { v0 = lrelu(v0); v1 = lrelu(v1); v2 = lrelu(v2); v3 = lrelu(v3); }
            if (r1 < nrows) *(float2*)(Out + r1 * 128 + n) = make_float2(v0, v1);
            if (r1 + 8 < nrows) *(float2*)(Out + (r1 + 8) * 128 + n) = make_float2(v2, v3);
        }
    }
}

__global__ __launch_bounds__(256, 2)
void gemm_node_tc(const float* __restrict__ A, const float* __restrict__ W,
                  const float* __restrict__ bias, float* __restrict__ Out,
                  int nrows, int act)
{
    extern __shared__ float smem[];
    gemm_node_body(A, W, bias, Out, nrows, act, blockIdx.x, (char*)smem);
}

__global__ __launch_bounds__(256, 2)
void gemm_node_dual(const float* __restrict__ A0, const float* __restrict__ W0,
                    const float* __restrict__ b0, float* __restrict__ O0,
                    const float* __restrict__ A1, const float* __restrict__ W1,
                    const float* __restrict__ b1, float* __restrict__ O1,
                    int nrows, int nb)
{
    extern __shared__ float smem[];
    if (blockIdx.x < nb)
        gemm_node_body(A0, W0, b0, O0, nrows, 0, blockIdx.x, (char*)smem);
    else
        gemm_node_body(A1, W1, b1, O1, nrows, 0, blockIdx.x - nb, (char*)smem);
}

// =======================================================================
// Edge scoring: warp-specialized, CSR-ordered tiles, hi fp32-acc + lo fp16-acc.
// =======================================================================
#define ES_SMEM_BYTES 165888

__device__ __forceinline__ void gather_csr(int e0, char* a_hi, char* a_lo, int tid2)
{
    const float4* hs4 = (const float4*)g_hs;
    const float4* hd4 = (const float4*)g_hd;
    const int rbase = tid2 >> 4;   // 0..15
    const int c8 = tid2 & 15;      // 8-col group

#pragma unroll
    for (int half = 0; half < 2; ++half) {
        int rr[4], sis[4], dis[4];
#pragma unroll
        for (int q = 0; q < 4; ++q) {
            rr[q] = (half * 4 + q) * 16 + rbase;
            int slot = e0 + rr[q];
            sis[q] = __ldg(&g_srcp[slot]);
            dis[q] = __ldg(&g_dstp[slot]);
        }
        float4 u0[4], u1[4], v0[4], v1[4];
#pragma unroll
        for (int q = 0; q < 4; ++q) {
            u0[q] = hs4[sis[q] * 32 + c8 * 2];
            u1[q] = hs4[sis[q] * 32 + c8 * 2 + 1];
            v0[q] = hd4[dis[q] * 32 + c8 * 2];
            v1[q] = hd4[dis[q] * 32 + c8 * 2 + 1];
        }
#pragma unroll
        for (int q = 0; q < 4; ++q) {
            float t0 = lrelu(u0[q].x + v0[q].x), t1 = lrelu(u0[q].y + v0[q].y);
            float t2 = lrelu(u0[q].z + v0[q].z), t3 = lrelu(u0[q].w + v0[q].w);
            float t4 = lrelu(u1[q].x + v1[q].x), t5 = lrelu(u1[q].y + v1[q].y);
            float t6 = lrelu(u1[q].z + v1[q].z), t7 = lrelu(u1[q].w + v1[q].w);
            uint4 hi, lo;
            split2h(t0, t1, hi.x, lo.x);
            split2h(t2, t3, hi.y, lo.y);
            split2h(t4, t5, hi.z, lo.z);
            split2h(t6, t7, hi.w, lo.w);
            uint32_t off = swz_off(rr[q], c8 * 8) * 2;   // 16B-aligned
            *(uint4*)(a_hi + off) = hi;
            *(uint4*)(a_lo + off) = lo;
        }
    }
}

__global__ __launch_bounds__(512, 1)
void edge_score_mma(const float* __restrict__ Wa1, const float* __restrict__ ba1,
                    const float* __restrict__ Wa2, const float* __restrict__ ba2)
{
    extern __shared__ float smem[];
    char* smc = (char*)smem;
    char* sW = smc;                    // 32KB (W_a1 fp16)
    char* sA_base = smc + 32768;       // 2 bufs x (hi 32KB + lo 32KB)
    float* sb1 = (float*)(smc + 163840);
    float* sw2 = (float*)(smc + 164352);
    float* sRed = (float*)(smc + 164864);  // 128 x 2

    const int tid = threadIdx.x;
    const int wid = tid >> 5;
    const int lane = tid & 31;
    const bool consumer = (wid < 8);

    for (int i = tid; i < D * D; i += 512) {
        int k = i >> 7, n = i & 127;
        ((__half*)sW)[swz_off(k, n)] = __float2half_rn(Wa1[i]);
    }
    if (tid < 128) { sb1[tid] = ba1[tid]; sw2[tid] = Wa2[tid]; }

    const float bias2 = ba2[0];
    const int rg = wid & 3, cg = wid >> 2;
    const int row_lo = (lane & 7) + ((lane >> 3) & 1) * 8;
    const int acg = (lane >> 4) & 1;
    const int x7 = lane & 7;
    const int g = lane >> 2;
    const int tig = lane & 3;
    const uint32_t sW_b = smem_u32(sW);
    const uint32_t sA_b = smem_u32(sA_base);
    const int tid2 = tid - 256;

    const int bid = blockIdx.x;
    const int grid = gridDim.x;

    if (!consumer && bid < NTILES)
        gather_csr(bid * 128, sA_base, sA_base + 32768, tid2);
    __syncthreads();

    int buf = 0;
    for (int tile = bid; tile < NTILES; tile += grid) {
        if (consumer) {
            const uint32_t cur_hi = sA_b + (uint32_t)buf * 65536u;
            const uint32_t cur_lo = cur_hi + 32768u;

            float acc[2][8][4];
            uint32_t lacc[2][8][2];
#pragma unroll
            for (int rc = 0; rc < 2; ++rc)
#pragma unroll
                for (int np = 0; np < 8; ++np) {
#pragma unroll
                    for (int j = 0; j < 4; ++j) acc[rc][np][j] = 0.f;
                    lacc[rc][np][0] = 0u; lacc[rc][np][1] = 0u;
                }

#pragma unroll
            for (int ks = 0; ks < 8; ++ks) {
                uint32_t ah[2][4], al[2][4];
#pragma unroll
                for (int rc = 0; rc < 2; ++rc) {
                    uint32_t a_off = (uint32_t)((rg * 32 + rc * 16 + row_lo) << 8)
                                   + (uint32_t)((((2 * ks + acg) ^ x7) << 4));
                    LDSM_X4(ah[rc][0], ah[rc][1], ah[rc][2], ah[rc][3], cur_hi + a_off);
                    LDSM_X4(al[rc][0], al[rc][1], al[rc][2], al[rc][3], cur_lo + a_off);
                }
                const int bk = ks * 16 + row_lo;
#pragma unroll
                for (int p = 0; p < 4; ++p) {
                    int cidx = 2 * (cg * 4 + p) + acg;
                    uint32_t b_off = (uint32_t)(bk << 8) + (uint32_t)(((cidx ^ x7) << 4));
                    uint32_t bh0, bh1, bh2, bh3;
                    LDSM_X4_T(bh0, bh1, bh2, bh3, sW_b + b_off);
#pragma unroll
                    for (int rc = 0; rc < 2; ++rc) {
                        float* c0 = acc[rc][2 * p];
                        float* c1 = acc[rc][2 * p + 1];
                        MMA_F16(c0[0], c0[1], c0[2], c0[3], ah[rc][0], ah[rc][1], ah[rc][2], ah[rc][3], bh0, bh1);
                        MMA_F16_ACCH(lacc[rc][2 * p][0], lacc[rc][2 * p][1],
                                     al[rc][0], al[rc][1], al[rc][2], al[rc][3], bh0, bh1);
                        MMA_F16(c1[0], c1[1], c1[2], c1[3], ah[rc][0], ah[rc][1], ah[rc][2], ah[rc][3], bh2, bh3);
                        MMA_F16_ACCH(lacc[rc][2 * p + 1][0], lacc[rc][2 * p + 1][1],
                                     al[rc][0], al[rc][1], al[rc][2], al[rc][3], bh2, bh3);
                    }
                }
            }

            // epilogue
#pragma unroll
            for (int rc = 0; rc < 2; ++rc) {
                float p0 = 0.f, p1 = 0.f;
#pragma unroll
                for (int np = 0; np < 8; ++np) {
                    int n = cg * 64 + np * 8 + tig * 2;
                    float b0 = sb1[n], b1 = sb1[n + 1];
                    float w0 = sw2[n], w1 = sw2[n + 1];
                    float v0 = acc[rc][np][0] + h2lo(lacc[rc][np][0]);
                    float v1 = acc[rc][np][1] + h2hi(lacc[rc][np][0]);
                    float v2 = acc[rc][np][2] + h2lo(lacc[rc][np][1]);
                    float v3 = acc[rc][np][3] + h2hi(lacc[rc][np][1]);
                    p0 += lrelu(v0 + b0) * w0 + lrelu(v1 + b1) * w1;
                    p1 += lrelu(v2 + b0) * w0 + lrelu(v3 + b1) * w1;
                }
                p0 += __shfl_xor_sync(0xffffffffu, p0, 1);
                p0 += __shfl_xor_sync(0xffffffffu, p0, 2);
                p1 += __shfl_xor_sync(0xffffffffu, p1, 1);
                p1 += __shfl_xor_sync(0xffffffffu, p1, 2);
                if (tig == 0) {
                    int row = rg * 32 + rc * 16 + g;
                    sRed[row * 2 + cg] = p0;
                    sRed[(row + 8) * 2 + cg] = p1;
                }
            }
            asm volatile("bar.sync 1, 256;" ::: "memory");
            if (tid < 128)
                g_score[tile * 128 + tid] = sRed[tid * 2] + sRed[tid * 2 + 1] + bias2;
        } else {
            const int nxt = tile + grid;
            if (nxt < NTILES) {
                char* nxt_hi = sA_base + (buf ^ 1) * 65536;
                gather_csr(nxt * 128, nxt_hi, nxt_hi + 32768, tid2);
            }
        }
        __syncthreads();
        buf ^= 1;
    }
}

// ---------------- CSR build ----------------
__global__ void k_zero()
{
    int i = blockIdx.x * 256 + threadIdx.x;
    if (i < NDST) { g_count[i] = 0; g_cursor[i] = 0; }
}

__global__ void k_hist(const int* __restrict__ dst_idx)
{
    int e = blockIdx.x * 256 + threadIdx.x;
    if (e < NEDGE) atomicAdd(&g_count[dst_idx[e]], 1);
}

__global__ void k_scan1()
{
    int tid = threadIdx.x;
    int gid = blockIdx.x * 1024 + tid;
    int v = (gid < NDST) ? g_count[gid] : 0;
    int lane = tid & 31, w = tid >> 5;
    int x = v;
#pragma unroll
    for (int o = 1; o < 32; o <<= 1) {
        int y = __shfl_up_sync(0xffffffffu, x, o);
        if (lane >= o) x += y;
    }
    __shared__ int ws[32];
    if (lane == 31) ws[w] = x;
    __syncthreads();
    if (w == 0) {
        int y = ws[lane];
#pragma unroll
        for (int o = 1; o < 32; o <<= 1) {
            int z = __shfl_up_sync(0xffffffffu, y, o);
            if (lane >= o) y += z;
        }
        ws[lane] = y;
    }
    __syncthreads();
    int pref = (w > 0) ? ws[w - 1] : 0;
    int incl = x + pref;
    if (gid < NDST) g_offset[gid] = incl - v;
    if (tid == 1023) g_bsums[blockIdx.x] = incl;
}

__global__ void k_scan2(int nblocks)
{
    int tid = threadIdx.x;
    int v = (tid < nblocks) ? g_bsums[tid] : 0;
    int lane = tid & 31, w = tid >> 5;
    int x = v;
#pragma unroll
    for (int o = 1; o < 32; o <<= 1) {
        int y = __shfl_up_sync(0xffffffffu, x, o);
        if (lane >= o) x += y;
    }
    __shared__ int ws[2];
    if (lane == 31) ws[w] = x;
    __syncthreads();
    if (w == 1) x += ws[0];
    g_bsums2[tid] = x - v;
}

__global__ void k_scan3()
{
    int gid = blockIdx.x * 1024 + threadIdx.x;
    if (gid < NDST) g_offset[gid] += g_bsums2[blockIdx.x];
    if (gid == 0) g_offset[NDST] = NEDGE;
}

__global__ void k_scatter(const int* __restrict__ dst_idx, const int* __restrict__ src_idx)
{
    int e = blockIdx.x * 256 + threadIdx.x;
    if (e < NEDGE) {
        int d = dst_idx[e];
        int p = atomicAdd(&g_cursor[d], 1);
        int slot = g_offset[d] + p;
        g_srcp[slot] = src_idx[e];
        g_dstp[slot] = d;
    }
}

// ---------------- softmax + aggregate ----------------
__global__ void k_aggregate()
{
    int gw = (blockIdx.x * blockDim.x + threadIdx.x) >> 5;
    int lane = threadIdx.x & 31;
    if (gw >= NDST) return;
    int beg = g_offset[gw], end = g_offset[gw + 1];

    const float4* hs4 = (const float4*)g_hs;
    const float4* hd4 = (const float4*)g_hd;
    float4 acc = make_float4(0.f, 0.f, 0.f, 0.f);

    if (end > beg) {
        float m = __int_as_float(0xff800000);
        for (int i = beg + lane; i < end; i += 32)
            m = fmaxf(m, g_score[i]);
#pragma unroll
        for (int o = 16; o; o >>= 1) m = fmaxf(m, __shfl_xor_sync(0xffffffffu, m, o));

        float dsum = 0.f;
        for (int i = beg + lane; i < end; i += 32)
            dsum += __expf(g_score[i] - m);
#pragma unroll
        for (int o = 16; o; o >>= 1) dsum += __shfl_xor_sync(0xffffffffu, dsum, o);
        float inv = 1.f / dsum;

        int s_nx = g_srcp[beg];
        float sc_nx = g_score[beg];
        for (int i = beg; i < end; ++i) {
            int s = s_nx;
            float sc = sc_nx;
            if (i + 1 < end) { s_nx = g_srcp[i + 1]; sc_nx = g_score[i + 1]; }
            float w = __expf(sc - m) * inv;
            float4 h = hs4[s * 32 + lane];
            acc.x += w * h.x; acc.y += w * h.y; acc.z += w * h.z; acc.w += w * h.w;
        }
        float4 hv = hd4[gw * 32 + lane];
        acc.x += hv.x; acc.y += hv.y; acc.z += hv.z; acc.w += hv.w;
    }
    ((float4*)g_nf)[gw * 32 + lane] = acc;
}

// ---------------- launch ----------------
extern "C" void kernel_launch(void* const* d_in, const int* in_sizes, int n_in,
                              void* d_out, int out_size)
{
    const float* feat_src = (const float*)d_in[0];
    const float* feat_dst = (const float*)d_in[1];
    const int*   src_idx  = (const int*)d_in[2];
    const int*   dst_idx  = (const int*)d_in[3];
    const float* W_src = (const float*)d_in[4];
    const float* b_src = (const float*)d_in[5];
    const float* W_dst = (const float*)d_in[6];
    const float* b_dst = (const float*)d_in[7];
    const float* W_a1  = (const float*)d_in[8];
    const float* b_a1  = (const float*)d_in[9];
    const float* W_a2  = (const float*)d_in[10];
    const float* b_a2  = (const float*)d_in[11];
    const float* W_out = (const float*)d_in[12];
    const float* b_out = (const float*)d_in[13];
    float* out = (float*)d_out;

    float *hs_p, *hd_p, *nf_p;
    cudaGetSymbolAddress((void**)&hs_p, g_hs);
    cudaGetSymbolAddress((void**)&hd_p, g_hd);
    cudaGetSymbolAddress((void**)&nf_p, g_nf);

    int nsm = 148;
    cudaDeviceGetAttribute(&nsm, cudaDevAttrMultiProcessorCount, 0);
    if (nsm <= 0 || nsm > NTILES) nsm = 148;

    cudaFuncSetAttribute(gemm_node_tc, cudaFuncAttributeMaxDynamicSharedMemorySize, GN_SMEM);
    cudaFuncSetAttribute(gemm_node_dual, cudaFuncAttributeMaxDynamicSharedMemorySize, GN_SMEM);
    cudaFuncSetAttribute(edge_score_mma, cudaFuncAttributeMaxDynamicSharedMemorySize, ES_SMEM_BYTES);

    const int gemm_blocks = (NSRC + 127) / 128;
    const int scan_blocks = (NDST + 1023) / 1024;

    // persistent side stream + events for the CSR fork (created once; no device mem)
    static cudaStream_t s_csr = nullptr;
    static cudaEvent_t ev_fork = nullptr, ev_join = nullptr;
    if (!s_csr) {
        cudaStreamCreateWithFlags(&s_csr, cudaStreamNonBlocking);
        cudaEventCreateWithFlags(&ev_fork, cudaEventDisableTiming);
        cudaEventCreateWithFlags(&ev_join, cudaEventDisableTiming);
    }

    // fork: CSR build on side stream, node GEMMs on main stream (independent)
    cudaEventRecord(ev_fork, 0);
    cudaStreamWaitEvent(s_csr, ev_fork, 0);

    k_zero<<<(NDST + 255) / 256, 256, 0, s_csr>>>();
    k_hist<<<(NEDGE + 255) / 256, 256, 0, s_csr>>>(dst_idx);
    k_scan1<<<scan_blocks, 1024, 0, s_csr>>>();
    k_scan2<<<1, 64, 0, s_csr>>>(scan_blocks);
    k_scan3<<<scan_blocks, 1024, 0, s_csr>>>();
    k_scatter<<<(NEDGE + 255) / 256, 256, 0, s_csr>>>(dst_idx, src_idx);
    cudaEventRecord(ev_join, s_csr);

    gemm_node_dual<<<2 * gemm_blocks, 256, GN_SMEM>>>(
        feat_src, W_src, b_src, hs_p,
        feat_dst, W_dst, b_dst, hd_p, NSRC, gemm_blocks);

    // join: edge kernel needs both hs/hd and CSR arrays
    cudaStreamWaitEvent(0, ev_join, 0);

    edge_score_mma<<<nsm, 512, ES_SMEM_BYTES>>>(W_a1, b_a1, W_a2, b_a2);

    k_aggregate<<<(NDST * 32 + 255) / 256, 256>>>();

    gemm_node_tc<<<gemm_blocks, 256, GN_SMEM>>>(nf_p, W_out, b_out, out, NDST, 1);
}